// round 8
// baseline (speedup 1.0000x reference)
#include <cuda_runtime.h>
#include <cuda_fp16.h>
#include <cstdint>

#define HID    512
#define BSZ    256
#define NROWS  (BSZ * BSZ)      // 65536
#define TILE_M 128
#define TILE_N 128
#define KC     64               // k per chunk (128B rows)
#define NCH    (HID / KC)       // 8 chunks

// Stage: A(128x64 fp16)=16K | W(128x64)=16K = 32K; 3 stages; + s_hx 2K
#define STAGE_BYTES 32768
#define SMEM_HX     98304
#define SMEM_BYTES  100352

// ---------------- device scratch ----------------
__device__ __align__(128) float g_hx[BSZ * HID];
__device__ __align__(128) float g_hy[BSZ * HID];
__device__ __align__(128) __half g_ah[NROWS * HID];          // layer1 output = layer2 input
__device__ __align__(128) __half g_wh[2][HID * HID];         // [n][k] transposed fp16
__device__ __align__(128) float g_part[4][NROWS];            // per-n-tile W3 partial sums

// ---------------- helpers ----------------
__device__ __forceinline__ uint32_t smem_u32(const void* p) {
    return (uint32_t)__cvta_generic_to_shared(p);
}
__device__ __forceinline__ void cp16(uint32_t dst, const void* src) {
    asm volatile("cp.async.cg.shared.global [%0], [%1], 16;" :: "r"(dst), "l"(src));
}
#define CP_COMMIT() asm volatile("cp.async.commit_group;")
#define CP_WAIT(n)  asm volatile("cp.async.wait_group %0;" :: "n"(n))

__device__ __forceinline__ uint32_t swz(uint32_t o) { return o ^ ((o >> 3) & 0x70); }

__device__ __forceinline__ void ldsm4(uint32_t& r0, uint32_t& r1, uint32_t& r2, uint32_t& r3,
                                      uint32_t addr) {
    asm volatile("ldmatrix.sync.aligned.m8n8.x4.shared.b16 {%0,%1,%2,%3}, [%4];"
                 : "=r"(r0), "=r"(r1), "=r"(r2), "=r"(r3) : "r"(addr));
}
__device__ __forceinline__ void mma16816(float* c, const uint32_t* a, uint32_t b0, uint32_t b1) {
    asm volatile("mma.sync.aligned.m16n8k16.row.col.f32.f16.f16.f32 "
                 "{%0,%1,%2,%3}, {%4,%5,%6,%7}, {%8,%9}, {%0,%1,%2,%3};"
                 : "+f"(c[0]), "+f"(c[1]), "+f"(c[2]), "+f"(c[3])
                 : "r"(a[0]), "r"(a[1]), "r"(a[2]), "r"(a[3]), "r"(b0), "r"(b1));
}

// ---------------- prep: transpose W1/W2 to fp16, coalesced via SMEM tiles ----------------
// grid = 16*16*2 blocks; block = 256 thr; each handles a 32x32 tile
__global__ void __launch_bounds__(256) prep_w_kernel(const float* __restrict__ W1,
                                                     const float* __restrict__ W2) {
    __shared__ float tile[32][33];
    const int b = blockIdx.x;
    const int which = b >> 8;
    const int kb = ((b >> 4) & 15) * 32;
    const int nb = (b & 15) * 32;
    const float* W = which ? W2 : W1;
    const int tid = threadIdx.x;
    const int r = tid >> 3, c = (tid & 7) * 4;
    // coalesced read: W[kb+r][nb+c .. c+3]
    float4 v = *(const float4*)(W + (size_t)(kb + r) * HID + nb + c);
    tile[r][c] = v.x; tile[r][c + 1] = v.y; tile[r][c + 2] = v.z; tile[r][c + 3] = v.w;
    __syncthreads();
    // coalesced write: g_wh[nb+r][kb+c .. c+3]  (half4 = 8B)
    __half h[4];
#pragma unroll
    for (int q = 0; q < 4; ++q) h[q] = __float2half(tile[c + q][r]);
    *(uint2*)(&g_wh[which][(size_t)(nb + r) * HID + kb + c]) = *(uint2*)h;
}

// ---------------- proj: hx = x@Wx + b0, hy = y@Wy (4 rows per CTA) ----------------
__global__ void __launch_bounds__(128, 8) proj_kernel(
    const float* __restrict__ x, const float* __restrict__ y,
    const float* __restrict__ Wx, const float* __restrict__ Wy,
    const float* __restrict__ b0)
{
    __shared__ float sx[4][128];
    const int b = blockIdx.x, tid = threadIdx.x;
    const int r0 = b * 4;
    const float* src; const float* W; float* dst; bool addb;
    if (r0 < BSZ) { src = x + (size_t)r0 * 128;         W = Wx; dst = g_hx + (size_t)r0 * HID;         addb = true;  }
    else          { src = y + (size_t)(r0 - BSZ) * 128; W = Wy; dst = g_hy + (size_t)(r0 - BSZ) * HID; addb = false; }
#pragma unroll
    for (int rr = 0; rr < 4; ++rr) sx[rr][tid] = src[rr * 128 + tid];
    __syncthreads();
    const float4* W4 = (const float4*)W;
    float4 acc[4];
#pragma unroll
    for (int rr = 0; rr < 4; ++rr) acc[rr] = make_float4(0.f, 0.f, 0.f, 0.f);
#pragma unroll 4
    for (int k = 0; k < 128; ++k) {
        float4 w = W4[k * (HID / 4) + tid];
#pragma unroll
        for (int rr = 0; rr < 4; ++rr) {
            float xv = sx[rr][k];
            acc[rr].x = fmaf(xv, w.x, acc[rr].x); acc[rr].y = fmaf(xv, w.y, acc[rr].y);
            acc[rr].z = fmaf(xv, w.z, acc[rr].z); acc[rr].w = fmaf(xv, w.w, acc[rr].w);
        }
    }
    float4 bb = make_float4(0.f, 0.f, 0.f, 0.f);
    if (addb) bb = ((const float4*)b0)[tid];
#pragma unroll
    for (int rr = 0; rr < 4; ++rr) {
        float4 o = acc[rr];
        if (addb) { o.x += bb.x; o.y += bb.y; o.z += bb.z; o.w += bb.w; }
        ((float4*)(dst + (size_t)rr * HID))[tid] = o;
    }
}

// ---------------- GEMM layer (templated): fused h0 (FIRST) / fused W3 dot (LAST) ----------------
template<bool FIRST, bool LAST>
__global__ void __launch_bounds__(256, 2) layer_kernel(const float* __restrict__ bias,
                                                       const float* __restrict__ W3)
{
    extern __shared__ __align__(1024) char smem[];
    const uint32_t sbase = smem_u32(smem);
    float* s_hx = (float*)(smem + SMEM_HX);
    const int tid = threadIdx.x, wid = tid >> 5, lane = tid & 31;
    const int warp_m = wid & 1;
    const int warp_n = wid >> 1;
    const int row0 = (blockIdx.x >> 2) * TILE_M;
    const int n0 = (blockIdx.x & 3) * TILE_N;
    const int which = FIRST ? 0 : 1;
    const __half* __restrict__ Wp = g_wh[which];
    const int j0 = row0 & 255;            // FIRST: j range of this tile
    const int iidx = row0 >> 8;           // FIRST: x-row index

    const uint32_t aA = swz((uint32_t)((warp_m * 64 + (lane & 15)) * 128 + ((lane >> 4) & 1) * 16));
    const int nloc = (lane & 7) + ((lane >> 4) << 3);
    const uint32_t aB = swz((uint32_t)((warp_n * 32 + nloc) * 128 + ((lane >> 3) & 1) * 16));

    float acc[4][4][4];
#pragma unroll
    for (int mg = 0; mg < 4; ++mg)
#pragma unroll
        for (int n8 = 0; n8 < 4; ++n8)
#pragma unroll
            for (int c = 0; c < 4; ++c) acc[mg][n8][c] = 0.f;

    auto load_chunk = [&](int t, int s) {
        uint32_t sb = sbase + s * STAGE_BYTES;
        if (FIRST) {
            // A computed on the fly: relu(hx + hy) -> fp16 STS
#pragma unroll
            for (int e = 0; e < 4; ++e) {
                int idx = tid + 256 * e;
                int r = idx >> 3, u = idx & 7;
                int k = t * KC + u * 8;
                const float4* hy4 = (const float4*)(g_hy + (size_t)(j0 + r) * HID + k);
                float4 y0 = hy4[0], y1 = hy4[1];
                float4 x0 = *(const float4*)(s_hx + k);
                float4 x1 = *(const float4*)(s_hx + k + 4);
                uint4 val;
                ((__half2*)&val)[0] = __floats2half2_rn(fmaxf(x0.x + y0.x, 0.f), fmaxf(x0.y + y0.y, 0.f));
                ((__half2*)&val)[1] = __floats2half2_rn(fmaxf(x0.z + y0.z, 0.f), fmaxf(x0.w + y0.w, 0.f));
                ((__half2*)&val)[2] = __floats2half2_rn(fmaxf(x1.x + y1.x, 0.f), fmaxf(x1.y + y1.y, 0.f));
                ((__half2*)&val)[3] = __floats2half2_rn(fmaxf(x1.z + y1.z, 0.f), fmaxf(x1.w + y1.w, 0.f));
                *(uint4*)(smem + (size_t)(s * STAGE_BYTES) + swz((uint32_t)(r * 128 + u * 16))) = val;
            }
            // W via cp.async: 1024 units / 256 thr = 4 each
#pragma unroll
            for (int e = 0; e < 4; ++e) {
                int idx = tid + 256 * e;
                int r = idx >> 3, u = idx & 7;
                uint32_t dst = sb + 16384 + swz((uint32_t)(r * 128 + u * 16));
                cp16(dst, Wp + (size_t)(n0 + r) * HID + t * KC + u * 8);
            }
        } else {
            // A + W via cp.async: 2048 units / 256 thr = 8 each
#pragma unroll
            for (int e = 0; e < 8; ++e) {
                int idx = tid + 256 * e;
                int part = idx >> 10;            // 0:A 1:W
                int r = (idx >> 3) & 127, u = idx & 7;
                uint32_t dst = sb + part * 16384 + swz((uint32_t)(r * 128 + u * 16));
                const __half* src = (part == 0) ? g_ah : Wp;
                int rbase = (part == 0) ? row0 : n0;
                cp16(dst, src + (size_t)(rbase + r) * HID + t * KC + u * 8);
            }
        }
        CP_COMMIT();
    };

    auto do_k16 = [&](uint32_t stg, int k16) {
        const uint32_t ko = (uint32_t)(k16 << 5);
        uint32_t bh[2][4];
#pragma unroll
        for (int ng = 0; ng < 2; ++ng) {
            uint32_t base = (stg + 16384 + aB + ng * 2048) ^ ko;
            ldsm4(bh[ng][0], bh[ng][1], bh[ng][2], bh[ng][3], base);
        }
#pragma unroll
        for (int mg = 0; mg < 4; ++mg) {
            uint32_t a[4];
            ldsm4(a[0], a[1], a[2], a[3], (stg + aA + mg * 2048) ^ ko);
#pragma unroll
            for (int ng = 0; ng < 2; ++ng)
#pragma unroll
                for (int j = 0; j < 2; ++j)
                    mma16816(acc[mg][ng * 2 + j], a, bh[ng][2 * j], bh[ng][2 * j + 1]);
        }
    };

    if (FIRST) {
        s_hx[tid]       = g_hx[(size_t)iidx * HID + tid];
        s_hx[tid + 256] = g_hx[(size_t)iidx * HID + tid + 256];
        __syncthreads();              // s_hx ready before any A staging
    }
    load_chunk(0, 0);
    load_chunk(1, 1);

    int sc = 0;                       // compute stage ring
    int sl = 2;                       // load stage ring
#pragma unroll 1
    for (int t = 0; t < NCH; ++t) {
        if (t < NCH - 1) CP_WAIT(1); else CP_WAIT(0);
        __syncthreads();              // publishes buf t, retires buf t-3
        const uint32_t stg = sbase + sc * STAGE_BYTES;
        do_k16(stg, 0);
        if (t + 2 < NCH) load_chunk(t + 2, sl);
        do_k16(stg, 1);
        do_k16(stg, 2);
        do_k16(stg, 3);
        if (++sc == 3) sc = 0;
        if (++sl == 3) sl = 0;
    }

    if (!LAST) {
        // epilogue: bias + relu -> fp16 -> g_ah
#pragma unroll
        for (int n8 = 0; n8 < 4; ++n8) {
            const int col = n0 + warp_n * 32 + n8 * 8 + (lane & 3) * 2;
            float2 bq = *(const float2*)(bias + col);
#pragma unroll
            for (int mg = 0; mg < 4; ++mg) {
                const int row = row0 + warp_m * 64 + mg * 16 + (lane >> 2);
                float* c = acc[mg][n8];
#pragma unroll
                for (int h = 0; h < 2; ++h) {
                    float v0 = fmaxf(c[2 * h]     + bq.x, 0.f);
                    float v1 = fmaxf(c[2 * h + 1] + bq.y, 0.f);
                    *(__half2*)(g_ah + (size_t)(row + h * 8) * HID + col) = __floats2half2_rn(v0, v1);
                }
            }
        }
    } else {
        // epilogue: rowsum += relu(acc + bias) * W3[col]; reduce; partials out
        float rowsum[4][2];
#pragma unroll
        for (int mg = 0; mg < 4; ++mg) { rowsum[mg][0] = 0.f; rowsum[mg][1] = 0.f; }
#pragma unroll
        for (int n8 = 0; n8 < 4; ++n8) {
            const int col = n0 + warp_n * 32 + n8 * 8 + (lane & 3) * 2;
            float2 bq = *(const float2*)(bias + col);
            float2 w3 = *(const float2*)(W3 + col);
#pragma unroll
            for (int mg = 0; mg < 4; ++mg) {
                float* c = acc[mg][n8];
#pragma unroll
                for (int h = 0; h < 2; ++h) {
                    float v0 = fmaxf(c[2 * h]     + bq.x, 0.f);
                    float v1 = fmaxf(c[2 * h + 1] + bq.y, 0.f);
                    rowsum[mg][h] = fmaf(v0, w3.x, fmaf(v1, w3.y, rowsum[mg][h]));
                }
            }
        }
#pragma unroll
        for (int mg = 0; mg < 4; ++mg)
#pragma unroll
            for (int h = 0; h < 2; ++h) {
                rowsum[mg][h] += __shfl_xor_sync(0xffffffffu, rowsum[mg][h], 1);
                rowsum[mg][h] += __shfl_xor_sync(0xffffffffu, rowsum[mg][h], 2);
            }
        float* s_part = (float*)smem;        // [4][128]
        __syncthreads();
        if ((lane & 3) == 0) {
#pragma unroll
            for (int mg = 0; mg < 4; ++mg)
#pragma unroll
                for (int h = 0; h < 2; ++h) {
                    int rl = warp_m * 64 + mg * 16 + (lane >> 2) + h * 8;
                    s_part[warp_n * 128 + rl] = rowsum[mg][h];
                }
        }
        __syncthreads();
        if (tid < 128) {
            float s = s_part[tid] + s_part[128 + tid] + s_part[256 + tid] + s_part[384 + tid];
            g_part[n0 >> 7][row0 + tid] = s;
        }
    }
}

// ---------------- combine: out[r] = sum_nt g_part[nt][r] + b3 ----------------
__global__ void __launch_bounds__(256) combine_kernel(const float* __restrict__ b3,
                                                      float* __restrict__ out) {
    int r = blockIdx.x * 256 + threadIdx.x;
    out[r] = g_part[0][r] + g_part[1][r] + g_part[2][r] + g_part[3][r] + b3[0];
}

// ---------------- launch ----------------
extern "C" void kernel_launch(void* const* d_in, const int* in_sizes, int n_in,
                              void* d_out, int out_size)
{
    const float* x  = (const float*)d_in[0];
    const float* y  = (const float*)d_in[1];
    const float* Wx = (const float*)d_in[2];
    const float* Wy = (const float*)d_in[3];
    const float* b0 = (const float*)d_in[4];
    const float* W1 = (const float*)d_in[5];
    const float* b1 = (const float*)d_in[6];
    const float* W2 = (const float*)d_in[7];
    const float* b2 = (const float*)d_in[8];
    const float* W3 = (const float*)d_in[9];
    const float* b3 = (const float*)d_in[10];
    float* out = (float*)d_out;

    cudaFuncSetAttribute(layer_kernel<true, false>,
                         cudaFuncAttributeMaxDynamicSharedMemorySize, SMEM_BYTES);
    cudaFuncSetAttribute(layer_kernel<false, true>,
                         cudaFuncAttributeMaxDynamicSharedMemorySize, SMEM_BYTES);

    prep_w_kernel<<<512, 256>>>(W1, W2);
    proj_kernel<<<(2 * BSZ) / 4, 128>>>(x, y, Wx, Wy, b0);
    layer_kernel<true, false><<<(NROWS / TILE_M) * 4, 256, SMEM_BYTES>>>(b1, nullptr);
    layer_kernel<false, true><<<(NROWS / TILE_M) * 4, 256, SMEM_BYTES>>>(b2, W3);
    combine_kernel<<<NROWS / 256, 256>>>(b3, out);
}

// round 9
// speedup vs baseline: 1.0168x; 1.0168x over previous
#include <cuda_runtime.h>
#include <cuda_fp16.h>
#include <cstdint>

#define HID    512
#define BSZ    256
#define NROWS  (BSZ * BSZ)      // 65536
#define TILE_M 128
#define TILE_N 128
#define KC     64               // k per chunk (128B rows)
#define NCH    (HID / KC)       // 8 chunks

// Stage: A(128x64 fp16)=16K | W(128x64)=16K = 32K; 2 stages; + s_hx 2K
#define STAGE_BYTES 32768
#define SMEM_HX     65536
#define SMEM_BYTES  67584

// ---------------- device scratch ----------------
__device__ __align__(128) float g_hx[BSZ * HID];
__device__ __align__(128) float g_hy[BSZ * HID];
__device__ __align__(128) __half g_ah[NROWS * HID];          // layer1 output = layer2 input
__device__ __align__(128) __half g_wh[2][HID * HID];         // [n][k] transposed fp16
__device__ __align__(128) float g_part[4][NROWS];            // per-n-tile W3 partial sums

// ---------------- helpers ----------------
__device__ __forceinline__ uint32_t smem_u32(const void* p) {
    return (uint32_t)__cvta_generic_to_shared(p);
}
__device__ __forceinline__ void cp16(uint32_t dst, const void* src) {
    asm volatile("cp.async.cg.shared.global [%0], [%1], 16;" :: "r"(dst), "l"(src));
}
#define CP_COMMIT() asm volatile("cp.async.commit_group;")
#define CP_WAIT(n)  asm volatile("cp.async.wait_group %0;" :: "n"(n))

__device__ __forceinline__ uint32_t swz(uint32_t o) { return o ^ ((o >> 3) & 0x70); }

__device__ __forceinline__ void ldsm4(uint32_t& r0, uint32_t& r1, uint32_t& r2, uint32_t& r3,
                                      uint32_t addr) {
    asm volatile("ldmatrix.sync.aligned.m8n8.x4.shared.b16 {%0,%1,%2,%3}, [%4];"
                 : "=r"(r0), "=r"(r1), "=r"(r2), "=r"(r3) : "r"(addr));
}
__device__ __forceinline__ void mma16816(float* c, const uint32_t* a, uint32_t b0, uint32_t b1) {
    asm volatile("mma.sync.aligned.m16n8k16.row.col.f32.f16.f16.f32 "
                 "{%0,%1,%2,%3}, {%4,%5,%6,%7}, {%8,%9}, {%0,%1,%2,%3};"
                 : "+f"(c[0]), "+f"(c[1]), "+f"(c[2]), "+f"(c[3])
                 : "r"(a[0]), "r"(a[1]), "r"(a[2]), "r"(a[3]), "r"(b0), "r"(b1));
}

// ---------------- fused init: W transpose tiles (blocks 0..511) + proj (blocks 512..575) ----------------
__global__ void __launch_bounds__(256) init_kernel(
    const float* __restrict__ x, const float* __restrict__ y,
    const float* __restrict__ Wx, const float* __restrict__ Wy,
    const float* __restrict__ b0,
    const float* __restrict__ W1, const float* __restrict__ W2)
{
    const int b = blockIdx.x;
    const int tid = threadIdx.x;
    if (b < 512) {
        // ---- 32x32 transpose tile: g_wh[which][n][k] = fp16(W[k][n]) ----
        __shared__ float tile[32][33];
        const int which = b >> 8;
        const int kb = ((b >> 4) & 15) * 32;
        const int nb = (b & 15) * 32;
        const float* W = which ? W2 : W1;
        const int r = tid >> 3, c = (tid & 7) * 4;
        float4 v = *(const float4*)(W + (size_t)(kb + r) * HID + nb + c);
        tile[r][c] = v.x; tile[r][c + 1] = v.y; tile[r][c + 2] = v.z; tile[r][c + 3] = v.w;
        __syncthreads();
        __half h[4];
#pragma unroll
        for (int q = 0; q < 4; ++q) h[q] = __float2half(tile[c + q][r]);
        *(uint2*)(&g_wh[which][(size_t)(nb + r) * HID + kb + c]) = *(uint2*)h;
    } else {
        // ---- proj: 8 rows per block; hx = x@Wx + b0 (rows<256), hy = y@Wy ----
        __shared__ float sx[8][128];
        const int r0 = (b - 512) * 8;                 // combined row index
        const float* src; const float* W; float* dst; bool addb;
        if (r0 < BSZ) { src = x + (size_t)r0 * 128;         W = Wx; dst = g_hx + (size_t)r0 * HID;         addb = true;  }
        else          { src = y + (size_t)(r0 - BSZ) * 128; W = Wy; dst = g_hy + (size_t)(r0 - BSZ) * HID; addb = false; }
#pragma unroll
        for (int q = 0; q < 4; ++q) {
            int idx = tid + 256 * q;                  // 1024 floats = 8 rows x 128
            sx[idx >> 7][idx & 127] = src[idx];
        }
        __syncthreads();
        const int tg = tid >> 7;                      // row half: rows tg*4 .. tg*4+3
        const int ctid = tid & 127;                   // float4 column
        const float4* W4 = (const float4*)W;
        float4 acc[4];
#pragma unroll
        for (int rr = 0; rr < 4; ++rr) acc[rr] = make_float4(0.f, 0.f, 0.f, 0.f);
#pragma unroll 4
        for (int k = 0; k < 128; ++k) {
            float4 w = W4[k * (HID / 4) + ctid];
#pragma unroll
            for (int rr = 0; rr < 4; ++rr) {
                float xv = sx[tg * 4 + rr][k];
                acc[rr].x = fmaf(xv, w.x, acc[rr].x); acc[rr].y = fmaf(xv, w.y, acc[rr].y);
                acc[rr].z = fmaf(xv, w.z, acc[rr].z); acc[rr].w = fmaf(xv, w.w, acc[rr].w);
            }
        }
        float4 bb = make_float4(0.f, 0.f, 0.f, 0.f);
        if (addb) bb = ((const float4*)b0)[ctid];
#pragma unroll
        for (int rr = 0; rr < 4; ++rr) {
            float4 o = acc[rr];
            if (addb) { o.x += bb.x; o.y += bb.y; o.z += bb.z; o.w += bb.w; }
            ((float4*)(dst + (size_t)(tg * 4 + rr) * HID))[ctid] = o;
        }
    }
}

// ---------------- GEMM layer (templated): fused h0 (FIRST) / fused W3 dot (LAST) ----------------
template<bool FIRST, bool LAST>
__global__ void __launch_bounds__(256, 2) layer_kernel(const float* __restrict__ bias,
                                                       const float* __restrict__ W3)
{
    extern __shared__ __align__(1024) char smem[];
    const uint32_t sbase = smem_u32(smem);
    float* s_hx = (float*)(smem + SMEM_HX);
    const int tid = threadIdx.x, wid = tid >> 5, lane = tid & 31;
    const int warp_m = wid & 1;
    const int warp_n = wid >> 1;
    const int row0 = (blockIdx.x >> 2) * TILE_M;
    const int n0 = (blockIdx.x & 3) * TILE_N;
    const int which = FIRST ? 0 : 1;
    const __half* __restrict__ Wp = g_wh[which];
    const int j0 = row0 & 255;            // FIRST: j range of this tile
    const int iidx = row0 >> 8;           // FIRST: x-row index

    const uint32_t aA = swz((uint32_t)((warp_m * 64 + (lane & 15)) * 128 + ((lane >> 4) & 1) * 16));
    const int nloc = (lane & 7) + ((lane >> 4) << 3);
    const uint32_t aB = swz((uint32_t)((warp_n * 32 + nloc) * 128 + ((lane >> 3) & 1) * 16));

    float acc[4][4][4];
#pragma unroll
    for (int mg = 0; mg < 4; ++mg)
#pragma unroll
        for (int n8 = 0; n8 < 4; ++n8)
#pragma unroll
            for (int c = 0; c < 4; ++c) acc[mg][n8][c] = 0.f;

    auto load_chunk = [&](int t, int s) {
        uint32_t sb = sbase + s * STAGE_BYTES;
        if (FIRST) {
            // A computed on the fly: relu(hx + hy) -> fp16 STS
#pragma unroll
            for (int e = 0; e < 4; ++e) {
                int idx = tid + 256 * e;
                int r = idx >> 3, u = idx & 7;
                int k = t * KC + u * 8;
                const float4* hy4 = (const float4*)(g_hy + (size_t)(j0 + r) * HID + k);
                float4 y0 = hy4[0], y1 = hy4[1];
                float4 x0 = *(const float4*)(s_hx + k);
                float4 x1 = *(const float4*)(s_hx + k + 4);
                uint4 val;
                ((__half2*)&val)[0] = __floats2half2_rn(fmaxf(x0.x + y0.x, 0.f), fmaxf(x0.y + y0.y, 0.f));
                ((__half2*)&val)[1] = __floats2half2_rn(fmaxf(x0.z + y0.z, 0.f), fmaxf(x0.w + y0.w, 0.f));
                ((__half2*)&val)[2] = __floats2half2_rn(fmaxf(x1.x + y1.x, 0.f), fmaxf(x1.y + y1.y, 0.f));
                ((__half2*)&val)[3] = __floats2half2_rn(fmaxf(x1.z + y1.z, 0.f), fmaxf(x1.w + y1.w, 0.f));
                *(uint4*)(smem + (size_t)(s * STAGE_BYTES) + swz((uint32_t)(r * 128 + u * 16))) = val;
            }
            // W via cp.async: 1024 units / 256 thr = 4 each
#pragma unroll
            for (int e = 0; e < 4; ++e) {
                int idx = tid + 256 * e;
                int r = idx >> 3, u = idx & 7;
                uint32_t dst = sb + 16384 + swz((uint32_t)(r * 128 + u * 16));
                cp16(dst, Wp + (size_t)(n0 + r) * HID + t * KC + u * 8);
            }
        } else {
            // A + W via cp.async: 2048 units / 256 thr = 8 each
#pragma unroll
            for (int e = 0; e < 8; ++e) {
                int idx = tid + 256 * e;
                int part = idx >> 10;            // 0:A 1:W
                int r = (idx >> 3) & 127, u = idx & 7;
                uint32_t dst = sb + part * 16384 + swz((uint32_t)(r * 128 + u * 16));
                const __half* src = (part == 0) ? g_ah : Wp;
                int rbase = (part == 0) ? row0 : n0;
                cp16(dst, src + (size_t)(rbase + r) * HID + t * KC + u * 8);
            }
        }
        CP_COMMIT();
    };

    auto do_k16 = [&](uint32_t stg, int k16) {
        const uint32_t ko = (uint32_t)(k16 << 5);
        uint32_t bh[2][4];
#pragma unroll
        for (int ng = 0; ng < 2; ++ng) {
            uint32_t base = (stg + 16384 + aB + ng * 2048) ^ ko;
            ldsm4(bh[ng][0], bh[ng][1], bh[ng][2], bh[ng][3], base);
        }
#pragma unroll
        for (int mg = 0; mg < 4; ++mg) {
            uint32_t a[4];
            ldsm4(a[0], a[1], a[2], a[3], (stg + aA + mg * 2048) ^ ko);
#pragma unroll
            for (int ng = 0; ng < 2; ++ng)
#pragma unroll
                for (int j = 0; j < 2; ++j)
                    mma16816(acc[mg][ng * 2 + j], a, bh[ng][2 * j], bh[ng][2 * j + 1]);
        }
    };

    if (FIRST) {
        s_hx[tid]       = g_hx[(size_t)iidx * HID + tid];
        s_hx[tid + 256] = g_hx[(size_t)iidx * HID + tid + 256];
    }
    __syncthreads();
    load_chunk(0, 0);

#pragma unroll 1
    for (int t = 0; t < NCH; ++t) {
        CP_WAIT(0);
        __syncthreads();                 // publishes buf t, retires buf t-1
        const uint32_t stg = sbase + (t & 1) * STAGE_BYTES;
        do_k16(stg, 0);
        if (t + 1 < NCH) load_chunk(t + 1, (t + 1) & 1);
        do_k16(stg, 1);
        do_k16(stg, 2);
        do_k16(stg, 3);
    }

    if (!LAST) {
        // epilogue: bias + relu -> fp16 -> g_ah
#pragma unroll
        for (int n8 = 0; n8 < 4; ++n8) {
            const int col = n0 + warp_n * 32 + n8 * 8 + (lane & 3) * 2;
            float2 bq = *(const float2*)(bias + col);
#pragma unroll
            for (int mg = 0; mg < 4; ++mg) {
                const int row = row0 + warp_m * 64 + mg * 16 + (lane >> 2);
                float* c = acc[mg][n8];
#pragma unroll
                for (int h = 0; h < 2; ++h) {
                    float v0 = fmaxf(c[2 * h]     + bq.x, 0.f);
                    float v1 = fmaxf(c[2 * h + 1] + bq.y, 0.f);
                    *(__half2*)(g_ah + (size_t)(row + h * 8) * HID + col) = __floats2half2_rn(v0, v1);
                }
            }
        }
    } else {
        // epilogue: rowsum += relu(acc + bias) * W3[col]; reduce; partials out
        float rowsum[4][2];
#pragma unroll
        for (int mg = 0; mg < 4; ++mg) { rowsum[mg][0] = 0.f; rowsum[mg][1] = 0.f; }
#pragma unroll
        for (int n8 = 0; n8 < 4; ++n8) {
            const int col = n0 + warp_n * 32 + n8 * 8 + (lane & 3) * 2;
            float2 bq = *(const float2*)(bias + col);
            float2 w3 = *(const float2*)(W3 + col);
#pragma unroll
            for (int mg = 0; mg < 4; ++mg) {
                float* c = acc[mg][n8];
#pragma unroll
                for (int h = 0; h < 2; ++h) {
                    float v0 = fmaxf(c[2 * h]     + bq.x, 0.f);
                    float v1 = fmaxf(c[2 * h + 1] + bq.y, 0.f);
                    rowsum[mg][h] = fmaf(v0, w3.x, fmaf(v1, w3.y, rowsum[mg][h]));
                }
            }
        }
#pragma unroll
        for (int mg = 0; mg < 4; ++mg)
#pragma unroll
            for (int h = 0; h < 2; ++h) {
                rowsum[mg][h] += __shfl_xor_sync(0xffffffffu, rowsum[mg][h], 1);
                rowsum[mg][h] += __shfl_xor_sync(0xffffffffu, rowsum[mg][h], 2);
            }
        float* s_part = (float*)smem;        // [4][128]
        __syncthreads();
        if ((lane & 3) == 0) {
#pragma unroll
            for (int mg = 0; mg < 4; ++mg)
#pragma unroll
                for (int h = 0; h < 2; ++h) {
                    int rl = warp_m * 64 + mg * 16 + (lane >> 2) + h * 8;
                    s_part[warp_n * 128 + rl] = rowsum[mg][h];
                }
        }
        __syncthreads();
        if (tid < 128) {
            float s = s_part[tid] + s_part[128 + tid] + s_part[256 + tid] + s_part[384 + tid];
            g_part[n0 >> 7][row0 + tid] = s;
        }
    }
}

// ---------------- combine: out[r] = sum_nt g_part[nt][r] + b3 ----------------
__global__ void __launch_bounds__(256) combine_kernel(const float* __restrict__ b3,
                                                      float* __restrict__ out) {
    int r = blockIdx.x * 256 + threadIdx.x;
    out[r] = g_part[0][r] + g_part[1][r] + g_part[2][r] + g_part[3][r] + b3[0];
}

// ---------------- launch ----------------
extern "C" void kernel_launch(void* const* d_in, const int* in_sizes, int n_in,
                              void* d_out, int out_size)
{
    const float* x  = (const float*)d_in[0];
    const float* y  = (const float*)d_in[1];
    const float* Wx = (const float*)d_in[2];
    const float* Wy = (const float*)d_in[3];
    const float* b0 = (const float*)d_in[4];
    const float* W1 = (const float*)d_in[5];
    const float* b1 = (const float*)d_in[6];
    const float* W2 = (const float*)d_in[7];
    const float* b2 = (const float*)d_in[8];
    const float* W3 = (const float*)d_in[9];
    const float* b3 = (const float*)d_in[10];
    float* out = (float*)d_out;

    cudaFuncSetAttribute(layer_kernel<true, false>,
                         cudaFuncAttributeMaxDynamicSharedMemorySize, SMEM_BYTES);
    cudaFuncSetAttribute(layer_kernel<false, true>,
                         cudaFuncAttributeMaxDynamicSharedMemorySize, SMEM_BYTES);

    init_kernel<<<576, 256>>>(x, y, Wx, Wy, b0, W1, W2);
    layer_kernel<true, false><<<(NROWS / TILE_M) * 4, 256, SMEM_BYTES>>>(b1, nullptr);
    layer_kernel<false, true><<<(NROWS / TILE_M) * 4, 256, SMEM_BYTES>>>(b2, W3);
    combine_kernel<<<NROWS / 256, 256>>>(b3, out);
}